// round 6
// baseline (speedup 1.0000x reference)
#include <cuda_runtime.h>
#include <cuda_bf16.h>

// Quaternion tensor product — CONVERGED, HBM-turnaround-wall-bound.
// Sweep evidence (R2-R5): HBM bandwidth invariant at ~7.1 TB/s (89% spec)
// across occ 28-59%, MLP 8-16, 128/256-bit accesses. 1.61 GB minimal traffic.
// Final config = R2 (best measured: 228.1us / 7140 GB/s): float4, 8
// front-batched streaming loads, early streaming stores; block=512.

__global__ __launch_bounds__(512) void quat_tp_kernel(
    const float4* __restrict__ in0,
    const float4* __restrict__ in1,
    float4* __restrict__ out)
{
    unsigned int idx = blockIdx.x * 512u + threadIdx.x;
    // batch = idx >> 5, group = idx & 31; base (float4 units) = batch*128 + group
    unsigned int base = ((idx >> 5) << 7) | (idx & 31u);

    // Front-batch all 8 independent loads (MLP=8), streaming (evict-first).
    float4 a0 = __ldcs(in0 + base);
    float4 a1 = __ldcs(in0 + base + 32);
    float4 a2 = __ldcs(in0 + base + 64);
    float4 a3 = __ldcs(in0 + base + 96);
    float4 b0 = __ldcs(in1 + base);
    float4 b1 = __ldcs(in1 + base + 32);
    float4 b2 = __ldcs(in1 + base + 64);
    float4 b3 = __ldcs(in1 + base + 96);

    float4 o;

    // o0 = a0*b0 - a1*b1 - a2*b2 - a3*b3
    o.x = a0.x*b0.x - a1.x*b1.x - a2.x*b2.x - a3.x*b3.x;
    o.y = a0.y*b0.y - a1.y*b1.y - a2.y*b2.y - a3.y*b3.y;
    o.z = a0.z*b0.z - a1.z*b1.z - a2.z*b2.z - a3.z*b3.z;
    o.w = a0.w*b0.w - a1.w*b1.w - a2.w*b2.w - a3.w*b3.w;
    __stcs(out + base, o);

    // o1 = a0*b1 + a1*b0 + a2*b3 - a3*b2
    o.x = a0.x*b1.x + a1.x*b0.x + a2.x*b3.x - a3.x*b2.x;
    o.y = a0.y*b1.y + a1.y*b0.y + a2.y*b3.y - a3.y*b2.y;
    o.z = a0.z*b1.z + a1.z*b0.z + a2.z*b3.z - a3.z*b2.z;
    o.w = a0.w*b1.w + a1.w*b0.w + a2.w*b3.w - a3.w*b2.w;
    __stcs(out + base + 32, o);

    // o2 = a0*b2 - a1*b3 + a2*b0 + a3*b1
    o.x = a0.x*b2.x - a1.x*b3.x + a2.x*b0.x + a3.x*b1.x;
    o.y = a0.y*b2.y - a1.y*b3.y + a2.y*b0.y + a3.y*b1.y;
    o.z = a0.z*b2.z - a1.z*b3.z + a2.z*b0.z + a3.z*b1.z;
    o.w = a0.w*b2.w - a1.w*b3.w + a2.w*b0.w + a3.w*b1.w;
    __stcs(out + base + 64, o);

    // o3 = a0*b3 + a1*b2 - a2*b1 + a3*b0
    o.x = a0.x*b3.x + a1.x*b2.x - a2.x*b1.x + a3.x*b0.x;
    o.y = a0.y*b3.y + a1.y*b2.y - a2.y*b1.y + a3.y*b0.y;
    o.z = a0.z*b3.z + a1.z*b2.z - a2.z*b1.z + a3.z*b0.z;
    o.w = a0.w*b3.w + a1.w*b2.w - a2.w*b1.w + a3.w*b0.w;
    __stcs(out + base + 96, o);
}

extern "C" void kernel_launch(void* const* d_in, const int* in_sizes, int n_in,
                              void* d_out, int out_size) {
    const float4* in0 = (const float4*)d_in[0];
    const float4* in1 = (const float4*)d_in[1];
    float4* out = (float4*)d_out;

    // threads = B * 32 = out_size / 16
    unsigned int threads_total = (unsigned int)((unsigned long long)out_size / 16ull);
    unsigned int grid = (threads_total + 511u) / 512u;
    quat_tp_kernel<<<grid, 512>>>(in0, in1, out);
}